// round 11
// baseline (speedup 1.0000x reference)
#include <cuda_runtime.h>

// Problem constants (fixed by the dataset)
#define T_LEN 4096
#define B_SZ  32
#define C_SZ  300
#define W_SZ  128
#define C4    (C_SZ / 4)      // 75 float4 per (t,b) row
#define ROW4  (B_SZ * C4)     // 2400 float4 per t-slice
#define NTHR  480             // 2400 = 480 * 5 exactly
#define UNROLL 5
#define GRID  608             // ~4 blocks/SM on 152-SM GB300; persistent
#define W_PAD 129             // 128 + 1: kills 32-way LDS bank conflicts

// Persistent fused kernel. Each block:
//  1. scans durations ONCE -> s_starts[32][129] (+ s_tot[32]) in shared
//  2. grid-strides over t-slices; per slice, warp 0 derives the 32 segment
//     positions via a 7-step binary search in shared (lane = sample), then
//     all 480 threads stream the slice with the proven R8 3-phase body.
// No wave transitions, prologue per slice ~2.4x cheaper, regs stay ~32-36.
__global__ void __launch_bounds__(NTHR) k_fused(const float4* __restrict__ x,
                                                const float4* __restrict__ pe,
                                                const int*    __restrict__ dur,
                                                float4*       __restrict__ out) {
    __shared__ int s_starts[B_SZ * W_PAD];
    __shared__ int s_tot[B_SZ];
    __shared__ int s_pos[B_SZ];

    const int warp = threadIdx.x >> 5;
    const int lane = threadIdx.x & 31;
    const int tid  = threadIdx.x;

    // ---- one-time scan: starts + totals into shared ----
    if (warp < 8) {
#pragma unroll
        for (int k = 0; k < 4; k++) {
            const int b = warp * 4 + k;
            int4 d4 = __ldg((const int4*)(dur + b * W_SZ + lane * 4));
            int s = d4.x + d4.y + d4.z + d4.w;
            int incl = s;
#pragma unroll
            for (int o = 1; o < 32; o <<= 1) {
                int vv = __shfl_up_sync(0xffffffffu, incl, o);
                if (lane >= o) incl += vv;
            }
            int base = incl - s;                    // exclusive prefix
            int* row = s_starts + b * W_PAD + lane * 4;
            row[0] = base;
            row[1] = base + d4.x;
            row[2] = base + d4.x + d4.y;
            row[3] = base + d4.x + d4.y + d4.z;
            if (lane == 31) s_tot[b] = incl;
        }
    }

    // ---- t-independent index math, hoisted out of the slice loop ----
    int bb[UNROLL], cc[UNROLL];
#pragma unroll
    for (int i = 0; i < UNROLL; i++) {
        int j = tid + i * NTHR;
        bb[i] = j / C4;                     // constant divide -> mul/shift
        cc[i] = j - bb[i] * C4;
    }
    __syncthreads();                        // starts/tot published

    // ---- persistent loop over t-slices ----
    for (int t = blockIdx.x; t < T_LEN; t += GRID) {
        // warp 0: segment position for all 32 samples (lane = sample)
        if (warp == 0) {
            const int* row = s_starts + lane * W_PAD;
            int lo = 0, hi = W_SZ - 1;
#pragma unroll
            for (int i = 0; i < 7; i++) {   // 128 -> 1 (row[0] == 0 <= t)
                int mid = (lo + hi + 1) >> 1;
                if (row[mid] <= t) lo = mid; else hi = mid - 1;
            }
            s_pos[lane] = (t < s_tot[lane]) ? (t - row[lo]) : -1;
        }
        __syncthreads();                    // s_pos ready

        const float4* xrow = x + (size_t)t * ROW4;
        float4*       orow = out + (size_t)t * ROW4;

        float4 v[UNROLL];
#pragma unroll
        for (int i = 0; i < UNROLL; i++)
            v[i] = __ldcs(xrow + tid + i * NTHR);      // streaming read
#pragma unroll
        for (int i = 0; i < UNROLL; i++) {
            int p = s_pos[bb[i]];
            if (p >= 0) {
                float4 pv = __ldcg(pe + p * C4 + cc[i]);  // L2-only gather
                v[i].x += pv.x; v[i].y += pv.y; v[i].z += pv.z; v[i].w += pv.w;
            }
        }
#pragma unroll
        for (int i = 0; i < UNROLL; i++)
            __stcs(orow + tid + i * NTHR, v[i]);       // streaming write

        __syncthreads();                    // protect s_pos before next write
    }
}

extern "C" void kernel_launch(void* const* d_in, const int* in_sizes, int n_in,
                              void* d_out, int out_size) {
    const float* x  = (const float*)d_in[0];
    const float* pe = (const float*)d_in[1];
    const int*   du = (const int*)d_in[2];
    // d_in[3] = train flag, unused by the reference math.
    k_fused<<<GRID, NTHR>>>((const float4*)x, (const float4*)pe, du, (float4*)d_out);
}

// round 12
// speedup vs baseline: 1.2291x; 1.2291x over previous
#include <cuda_runtime.h>

// Problem constants (fixed by the dataset)
#define T_LEN 4096
#define B_SZ  32
#define C_SZ  300
#define W_SZ  128
#define C4    (C_SZ / 4)     // 75 float4 per (t,b) row
#define ROW4  (B_SZ * C4)    // 2400 float4 per t-slice
#define NTHR  480            // 2400 = 480 * 5 exactly
#define UNROLL 5

// FINAL kernel (R8 structure; measured optimum, confirmed 3x at 51.7us).
// One block per t. Warps 0-7 compute the 32 per-sample segment positions
// (warp-scan of durations + ballot select of "largest start <= t"); then a
// 3-phase stream: batched __ldcs x-loads (MLP=5), branched L2-only pe
// gather + add, batched __stcs stores. regs=32, occ~78%, DRAM ~70% — the
// HBM read/write-mix ceiling (~5.6 TB/s) for this chip.
// Falsified alternatives: reg-hoisted loads (R4, occ collapse), T_PER=2
// (R5, regs 44), cp.async staging (R6, smem round-trip cost), branchless
// pe (R7, +50% L2 gathers), merged add+store (R9, STG inside branch),
// persistent blocks (R11, barrier lockstep kills cross-slice MLP).
__global__ void __launch_bounds__(NTHR) k_fused(const float4* __restrict__ x,
                                                const float4* __restrict__ pe,
                                                const int*    __restrict__ dur,
                                                float4*       __restrict__ out) {
    __shared__ int s_pos[B_SZ];
    const int t    = blockIdx.x;
    const int warp = threadIdx.x >> 5;
    const int lane = threadIdx.x & 31;
    const int tid  = threadIdx.x;

    // ---- prologue: segment position for 4 samples per warp (warps 0-7) ----
    if (warp < 8) {
#pragma unroll
        for (int k = 0; k < 4; k++) {
            const int b = warp * 4 + k;
            int4 d4 = __ldg((const int4*)(dur + b * W_SZ + lane * 4));
            int s = d4.x + d4.y + d4.z + d4.w;
            int incl = s;
#pragma unroll
            for (int o = 1; o < 32; o <<= 1) {
                int vv = __shfl_up_sync(0xffffffffu, incl, o);
                if (lane >= o) incl += vv;
            }
            int base = incl - s;                   // exclusive prefix across lanes
            int st0 = base;
            int st1 = base + d4.x;
            int st2 = st1 + d4.y;
            int st3 = st2 + d4.z;
            int tot = __shfl_sync(0xffffffffu, incl, 31);

            // Largest start <= t: starts nondecreasing across lanes.
            unsigned m = __ballot_sync(0xffffffffu, st0 <= t);
            int L = 31 - __clz(m);
            int loc = st0;
            if (st1 <= t) loc = st1;
            if (st2 <= t) loc = st2;
            if (st3 <= t) loc = st3;
            int seg = __shfl_sync(0xffffffffu, loc, L);

            if (lane == 0) s_pos[b] = (t < tot) ? (t - seg) : -1;
        }
    }
    __syncthreads();

    // ---- streaming add: exact unroll, batched x loads for MLP ----
    const float4* xrow = x + (size_t)t * ROW4;
    float4*       orow = out + (size_t)t * ROW4;

    float4 v[UNROLL];
    int    bb[UNROLL], cc[UNROLL];
#pragma unroll
    for (int i = 0; i < UNROLL; i++) {
        int j = tid + i * NTHR;
        bb[i] = j / C4;                    // constant divide -> mul/shift
        cc[i] = j - bb[i] * C4;
        v[i]  = __ldcs(xrow + j);          // streaming read (evict-first)
    }
#pragma unroll
    for (int i = 0; i < UNROLL; i++) {
        int p = s_pos[bb[i]];
        if (p >= 0) {
            float4 pv = __ldcg(pe + p * C4 + cc[i]);  // L2-only: no L1 pollution
            v[i].x += pv.x; v[i].y += pv.y; v[i].z += pv.z; v[i].w += pv.w;
        }
    }
#pragma unroll
    for (int i = 0; i < UNROLL; i++) {
        __stcs(orow + tid + i * NTHR, v[i]);          // streaming write
    }
}

extern "C" void kernel_launch(void* const* d_in, const int* in_sizes, int n_in,
                              void* d_out, int out_size) {
    const float* x  = (const float*)d_in[0];
    const float* pe = (const float*)d_in[1];
    const int*   du = (const int*)d_in[2];
    // d_in[3] = train flag, unused by the reference math.
    k_fused<<<T_LEN, NTHR>>>((const float4*)x, (const float4*)pe, du, (float4*)d_out);
}